// round 3
// baseline (speedup 1.0000x reference)
#include <cuda_runtime.h>
#include <cstdint>

#define T_SEQ 2048
#define BATCH 256
#define HID   64
#define INP   7
#define XSTEPS 64            // steps per prefetch block
#define XBLK_FLOATS (XSTEPS * INP)   // 448 floats per block in GMEM

typedef unsigned long long ull;

__device__ __forceinline__ ull fma2(ull a, ull b, ull c) {
    ull d;
    asm("fma.rn.f32x2 %0, %1, %2, %3;" : "=l"(d) : "l"(a), "l"(b), "l"(c));
    return d;
}
__device__ __forceinline__ ull add2(ull a, ull b) {
    ull d;
    asm("add.rn.f32x2 %0, %1, %2;" : "=l"(d) : "l"(a), "l"(b));
    return d;
}
__device__ __forceinline__ ull pack2(float lo, float hi) {
    ull d; asm("mov.b64 %0, {%1, %2};" : "=l"(d) : "f"(lo), "f"(hi)); return d;
}
__device__ __forceinline__ float2 unpack2(ull a) {
    float2 r; asm("mov.b64 {%0, %1}, %2;" : "=f"(r.x), "=f"(r.y) : "l"(a)); return r;
}
__device__ __forceinline__ float htanh(float x) {
    float y; asm("tanh.approx.f32 %0, %1;" : "=f"(y) : "f"(x)); return y;
}
__device__ __forceinline__ void cpa4(uint32_t dst_smem, const float* src) {
    asm volatile("cp.async.ca.shared.global [%0], [%1], 4;" :: "r"(dst_smem), "l"(src));
}
__device__ __forceinline__ void cp_commit() {
    asm volatile("cp.async.commit_group;" ::: "memory");
}
__device__ __forceinline__ void cp_wait0() {
    asm volatile("cp.async.wait_group 0;" ::: "memory");
}

// grid = 128 CTAs x 512 threads; CTA runs 2 independent batch chains
// (chain = tid>>8) with per-chain named barriers.
//
// Per chain: thread w in [0,256): unit u = w>>2, gate gi = w&3 (i,f,g,o),
// weight row r = gi*64+u. Per step: z_r = W_hh[r]·h + W_ih[r]·x + bias with
// packed f32x2 FMAs (weights in regs), unified activation m*tanh(s*z)+b via
// MUFU.TANH. The 4 gates of unit u live in one lane-nibble, so the state
// update exchanges them with 2 shuffle levels (no smem, no extra barrier);
// gi==0 lanes update c and write h into the alternate h buffer. ONE named
// barrier per step. x is streamed through a cp.async double-buffered 64-step
// ring (8-float padded rows => aligned LDS.128 reads; pad weight = 0).
//
// Backward direction = ONE LSTM step on x[T-1] from zero state; fused with
// the final linear as an epilogue.
struct ChainSmem {
    float h[2][64];            // double-buffered hidden state
    float hb[64];              // backward h (epilogue)
    float xring[2][XSTEPS * 8];// padded x ring, 2 blocks
};

__global__ void __launch_bounds__(512, 1)
bilstm_kernel(const float* __restrict__ x,      // [B,T,I]
              const float* __restrict__ Wih_f,  // [256,7]
              const float* __restrict__ Whh_f,  // [256,64]
              const float* __restrict__ bih_f,  // [256]
              const float* __restrict__ bhh_f,  // [256]
              const float* __restrict__ Wih_b,  // [256,7]
              const float* __restrict__ Whh_b,  // unused (h0 = 0 for single bwd step)
              const float* __restrict__ bih_b,  // [256]
              const float* __restrict__ bhh_b,  // [256]
              const float* __restrict__ Wlin,   // [3,128]
              const float* __restrict__ blin,   // [3]
              float* __restrict__ out)          // [B,3]
{
    __shared__ __align__(16) ChainSmem cs[2];

    const int tid   = threadIdx.x;
    const int chain = tid >> 8;
    const int w     = tid & 255;
    const int gi    = w & 3;
    const int u     = w >> 2;
    const int r     = gi * 64 + u;
    const int b     = blockIdx.x * 2 + chain;
    const int barid = 1 + chain;
    ChainSmem& S = cs[chain];

    const float* xb = x + (size_t)b * T_SEQ * INP;

    // smem u32 addresses for cp.async destinations
    const uint32_t ring0 = (uint32_t)__cvta_generic_to_shared(&S.xring[0][0]);
    const uint32_t ring1 = (uint32_t)__cvta_generic_to_shared(&S.xring[1][0]);

    // this thread's two ring elements: e0 = 2w, e1 = 2w+1 (512 floats/block)
    const int e0 = 2 * w, e1 = 2 * w + 1;
    const int s0 = e0 >> 3, j0 = e0 & 7;
    const int s1 = e1 >> 3, j1 = e1 & 7;

    // activation: gi==2 -> tanh(z); else sigmoid(z) = 0.5*tanh(0.5z)+0.5
    const float act_s = (gi == 2) ? 1.0f : 0.5f;
    const float act_m = (gi == 2) ? 1.0f : 0.5f;
    const float act_b = (gi == 2) ? 0.0f : 0.5f;

    // ---- weights into registers ----
    ull wrec[32];
    const ull* wrow = reinterpret_cast<const ull*>(Whh_f + r * HID);
#pragma unroll
    for (int m = 0; m < 32; m++) wrec[m] = wrow[m];

    float wih_s[8];
#pragma unroll
    for (int i = 0; i < INP; i++) wih_s[i] = Wih_f[r * INP + i];
    wih_s[7] = 0.0f;
    ull wih2[4];
#pragma unroll
    for (int m = 0; m < 4; m++) wih2[m] = pack2(wih_s[2 * m], wih_s[2 * m + 1]);

    const float bias = bih_f[r] + bhh_f[r];

    // ---- init: h=0, zero pad slots, prefetch blocks 0 and 1 ----
    if (w < 64) S.h[0][w] = 0.0f;
    if (w < 128) {  // zero the j==7 pad slot of every ring row (both buffers)
        int bufi = w >> 6, s = w & 63;
        S.xring[bufi][s * 8 + 7] = 0.0f;
    }
    if (j0 < 7) cpa4(ring0 + (uint32_t)e0 * 4, xb + s0 * INP + j0);
    if (j1 < 7) cpa4(ring0 + (uint32_t)e1 * 4, xb + s1 * INP + j1);
    cp_commit();
    if (j0 < 7) cpa4(ring1 + (uint32_t)e0 * 4, xb + XBLK_FLOATS + s0 * INP + j0);
    if (j1 < 7) cpa4(ring1 + (uint32_t)e1 * 4, xb + XBLK_FLOATS + s1 * INP + j1);
    cp_commit();
    cp_wait0();
    float c = 0.0f;
    __syncthreads();

    for (int t = 0; t < T_SEQ; t++) {
        if ((t & (XSTEPS - 1)) == 0 && t) {
            // block issued at previous boundary has had 64 steps to land
            cp_wait0();
            asm volatile("bar.sync %0, 256;" :: "r"(barid) : "memory");
            int nb = (t >> 6) + 1;
            if (nb < T_SEQ / XSTEPS) {
                uint32_t dst = (nb & 1) ? ring1 : ring0;
                const float* src = xb + (size_t)nb * XBLK_FLOATS;
                if (j0 < 7) cpa4(dst + (uint32_t)e0 * 4, src + s0 * INP + j0);
                if (j1 < 7) cpa4(dst + (uint32_t)e1 * 4, src + s1 * INP + j1);
            }
            cp_commit();
        }

        // z_r = W_hh[r]·h + W_ih[r]·x + bias
        ull acc0 = pack2(bias, 0.0f), acc1 = 0ull, acc2 = 0ull, acc3 = 0ull;
        const ulonglong2* h2 = reinterpret_cast<const ulonglong2*>(S.h[t & 1]);
#pragma unroll
        for (int m = 0; m < 8; m++) {
            ulonglong2 ha = h2[2 * m];
            ulonglong2 hb = h2[2 * m + 1];
            acc0 = fma2(wrec[4 * m + 0], ha.x, acc0);
            acc1 = fma2(wrec[4 * m + 1], ha.y, acc1);
            acc2 = fma2(wrec[4 * m + 2], hb.x, acc2);
            acc3 = fma2(wrec[4 * m + 3], hb.y, acc3);
        }
        {
            const ulonglong2* x2 = reinterpret_cast<const ulonglong2*>(
                &S.xring[(t >> 6) & 1][(t & 63) * 8]);
            ulonglong2 xv = x2[0];
            ulonglong2 xw = x2[1];
            acc0 = fma2(wih2[0], xv.x, acc0);
            acc1 = fma2(wih2[1], xv.y, acc1);
            acc2 = fma2(wih2[2], xw.x, acc2);
            acc3 = fma2(wih2[3], xw.y, acc3);
        }
        ull s2 = add2(add2(acc0, acc1), add2(acc2, acc3));
        float2 sf = unpack2(s2);
        float a = fmaf(act_m, htanh(act_s * (sf.x + sf.y)), act_b);

        // gather the nibble's 4 gates via 2 shuffle levels
        float r1 = __shfl_xor_sync(0xFFFFFFFFu, a, 1);
        float r2 = __shfl_xor_sync(0xFFFFFFFFu, a, 2);
        float r3 = __shfl_xor_sync(0xFFFFFFFFu, r1, 2);
        if (gi == 0) {
            // a=i, r1=f, r2=g, r3=o
            c = r1 * c + a * r2;
            S.h[(t & 1) ^ 1][u] = r3 * htanh(c);
        }
        asm volatile("bar.sync %0, 256;" :: "r"(barid) : "memory");
    }

    // ---- backward direction: ONE step on x[T-1] from zero state ----
    {
        const float* xl = &S.xring[1][63 * 8];   // t=2047 -> buf 1, slot 63
        float zb = bih_b[r] + bhh_b[r];
#pragma unroll
        for (int i = 0; i < INP; i++) zb += Wih_b[r * INP + i] * xl[i];
        float a = fmaf(act_m, htanh(act_s * zb), act_b);
        float r1 = __shfl_xor_sync(0xFFFFFFFFu, a, 1);
        float r2 = __shfl_xor_sync(0xFFFFFFFFu, a, 2);
        float r3 = __shfl_xor_sync(0xFFFFFFFFu, r1, 2);
        if (gi == 0) {
            float cb = a * r2;                 // f*c0 == 0
            S.hb[u] = r3 * htanh(cb);
        }
        asm volatile("bar.sync %0, 256;" :: "r"(barid) : "memory");
    }

    // ---- final linear: out[b] = W_lin @ concat(h_f, h_b) + b_lin ----
    // final forward h was written into S.h[0] (t=2047 writes buffer (2047&1)^1 = 0)
    if (w < 3) {
        float a = blin[w];
#pragma unroll 16
        for (int k = 0; k < 64; k++) a += Wlin[w * 128 + k] * S.h[0][k];
#pragma unroll 16
        for (int k = 0; k < 64; k++) a += Wlin[w * 128 + 64 + k] * S.hb[k];
        out[b * 3 + w] = a;
    }
}

extern "C" void kernel_launch(void* const* d_in, const int* in_sizes, int n_in,
                              void* d_out, int out_size) {
    (void)in_sizes; (void)n_in; (void)out_size;
    bilstm_kernel<<<BATCH / 2, 512>>>(
        (const float*)d_in[0],  (const float*)d_in[1], (const float*)d_in[2],
        (const float*)d_in[3],  (const float*)d_in[4], (const float*)d_in[5],
        (const float*)d_in[6],  (const float*)d_in[7], (const float*)d_in[8],
        (const float*)d_in[9],  (const float*)d_in[10], (float*)d_out);
}

// round 4
// speedup vs baseline: 1.6394x; 1.6394x over previous
#include <cuda_runtime.h>
#include <cstdint>

#define T_SEQ 2048
#define BATCH 256
#define HID   64
#define INP   7
#define XSTEPS 64            // steps per prefetch block
#define XBLK_FLOATS (XSTEPS * INP)   // 448 floats per block in GMEM

typedef unsigned long long ull;

__device__ __forceinline__ ull fma2(ull a, ull b, ull c) {
    ull d;
    asm("fma.rn.f32x2 %0, %1, %2, %3;" : "=l"(d) : "l"(a), "l"(b), "l"(c));
    return d;
}
__device__ __forceinline__ ull add2(ull a, ull b) {
    ull d;
    asm("add.rn.f32x2 %0, %1, %2;" : "=l"(d) : "l"(a), "l"(b));
    return d;
}
__device__ __forceinline__ ull pack2(float lo, float hi) {
    ull d; asm("mov.b64 %0, {%1, %2};" : "=l"(d) : "f"(lo), "f"(hi)); return d;
}
__device__ __forceinline__ float2 unpack2(ull a) {
    float2 r; asm("mov.b64 {%0, %1}, %2;" : "=f"(r.x), "=f"(r.y) : "l"(a)); return r;
}
__device__ __forceinline__ float htanh(float x) {
    float y; asm("tanh.approx.f32 %0, %1;" : "=f"(y) : "f"(x)); return y;
}
__device__ __forceinline__ void cpa4(uint32_t dst_smem, const float* src) {
    asm volatile("cp.async.ca.shared.global [%0], [%1], 4;" :: "r"(dst_smem), "l"(src));
}
__device__ __forceinline__ void cp_commit() {
    asm volatile("cp.async.commit_group;" ::: "memory");
}
__device__ __forceinline__ void cp_wait0() {
    asm volatile("cp.async.wait_group 0;" ::: "memory");
}

// grid = 128 CTAs x 512 threads; CTA runs 2 independent batch chains
// (chain = tid>>8) with per-chain named barriers.
//
// Per chain: thread w in [0,256): unit u = w>>2, gate gi = w&3 (i,f,g,o),
// weight row r = gi*64+u. Per step: z_r = W_hh[r]·h + W_ih[r]·x + bias with
// packed f32x2 FMAs (weights in regs), unified activation m*tanh(s*z)+b via
// MUFU.TANH. The 4 gates of unit u live in one lane-nibble, so the state
// update exchanges them with 2 shuffle levels (no smem, no extra barrier);
// gi==0 lanes update c and write h into the alternate h buffer. ONE named
// barrier per step. x is streamed through a cp.async double-buffered 64-step
// ring (8-float padded rows => aligned LDS.128 reads; pad weight = 0).
//
// Backward direction = ONE LSTM step on x[T-1] from zero state; fused with
// the final linear as an epilogue.
struct ChainSmem {
    float h[2][64];            // double-buffered hidden state
    float hb[64];              // backward h (epilogue)
    float xring[2][XSTEPS * 8];// padded x ring, 2 blocks
};

__global__ void __launch_bounds__(512, 1)
bilstm_kernel(const float* __restrict__ x,      // [B,T,I]
              const float* __restrict__ Wih_f,  // [256,7]
              const float* __restrict__ Whh_f,  // [256,64]
              const float* __restrict__ bih_f,  // [256]
              const float* __restrict__ bhh_f,  // [256]
              const float* __restrict__ Wih_b,  // [256,7]
              const float* __restrict__ Whh_b,  // unused (h0 = 0 for single bwd step)
              const float* __restrict__ bih_b,  // [256]
              const float* __restrict__ bhh_b,  // [256]
              const float* __restrict__ Wlin,   // [3,128]
              const float* __restrict__ blin,   // [3]
              float* __restrict__ out)          // [B,3]
{
    __shared__ __align__(16) ChainSmem cs[2];

    const int tid   = threadIdx.x;
    const int chain = tid >> 8;
    const int w     = tid & 255;
    const int gi    = w & 3;
    const int u     = w >> 2;
    const int r     = gi * 64 + u;
    const int b     = blockIdx.x * 2 + chain;
    const int barid = 1 + chain;
    ChainSmem& S = cs[chain];

    const float* xb = x + (size_t)b * T_SEQ * INP;

    // smem u32 addresses for cp.async destinations
    const uint32_t ring0 = (uint32_t)__cvta_generic_to_shared(&S.xring[0][0]);
    const uint32_t ring1 = (uint32_t)__cvta_generic_to_shared(&S.xring[1][0]);

    // this thread's two ring elements: e0 = 2w, e1 = 2w+1 (512 floats/block)
    const int e0 = 2 * w, e1 = 2 * w + 1;
    const int s0 = e0 >> 3, j0 = e0 & 7;
    const int s1 = e1 >> 3, j1 = e1 & 7;

    // activation: gi==2 -> tanh(z); else sigmoid(z) = 0.5*tanh(0.5z)+0.5
    const float act_s = (gi == 2) ? 1.0f : 0.5f;
    const float act_m = (gi == 2) ? 1.0f : 0.5f;
    const float act_b = (gi == 2) ? 0.0f : 0.5f;

    // ---- weights into registers ----
    ull wrec[32];
    const ull* wrow = reinterpret_cast<const ull*>(Whh_f + r * HID);
#pragma unroll
    for (int m = 0; m < 32; m++) wrec[m] = wrow[m];

    float wih_s[8];
#pragma unroll
    for (int i = 0; i < INP; i++) wih_s[i] = Wih_f[r * INP + i];
    wih_s[7] = 0.0f;
    ull wih2[4];
#pragma unroll
    for (int m = 0; m < 4; m++) wih2[m] = pack2(wih_s[2 * m], wih_s[2 * m + 1]);

    const float bias = bih_f[r] + bhh_f[r];

    // ---- init: h=0, zero pad slots, prefetch blocks 0 and 1 ----
    if (w < 64) S.h[0][w] = 0.0f;
    if (w < 128) {  // zero the j==7 pad slot of every ring row (both buffers)
        int bufi = w >> 6, s = w & 63;
        S.xring[bufi][s * 8 + 7] = 0.0f;
    }
    if (j0 < 7) cpa4(ring0 + (uint32_t)e0 * 4, xb + s0 * INP + j0);
    if (j1 < 7) cpa4(ring0 + (uint32_t)e1 * 4, xb + s1 * INP + j1);
    cp_commit();
    if (j0 < 7) cpa4(ring1 + (uint32_t)e0 * 4, xb + XBLK_FLOATS + s0 * INP + j0);
    if (j1 < 7) cpa4(ring1 + (uint32_t)e1 * 4, xb + XBLK_FLOATS + s1 * INP + j1);
    cp_commit();
    cp_wait0();
    float c = 0.0f;
    __syncthreads();

    for (int t = 0; t < T_SEQ; t++) {
        if ((t & (XSTEPS - 1)) == 0 && t) {
            // block issued at previous boundary has had 64 steps to land
            cp_wait0();
            asm volatile("bar.sync %0, 256;" :: "r"(barid) : "memory");
            int nb = (t >> 6) + 1;
            if (nb < T_SEQ / XSTEPS) {
                uint32_t dst = (nb & 1) ? ring1 : ring0;
                const float* src = xb + (size_t)nb * XBLK_FLOATS;
                if (j0 < 7) cpa4(dst + (uint32_t)e0 * 4, src + s0 * INP + j0);
                if (j1 < 7) cpa4(dst + (uint32_t)e1 * 4, src + s1 * INP + j1);
            }
            cp_commit();
        }

        // z_r = W_hh[r]·h + W_ih[r]·x + bias
        ull acc0 = pack2(bias, 0.0f), acc1 = 0ull, acc2 = 0ull, acc3 = 0ull;
        const ulonglong2* h2 = reinterpret_cast<const ulonglong2*>(S.h[t & 1]);
#pragma unroll
        for (int m = 0; m < 8; m++) {
            ulonglong2 ha = h2[2 * m];
            ulonglong2 hb = h2[2 * m + 1];
            acc0 = fma2(wrec[4 * m + 0], ha.x, acc0);
            acc1 = fma2(wrec[4 * m + 1], ha.y, acc1);
            acc2 = fma2(wrec[4 * m + 2], hb.x, acc2);
            acc3 = fma2(wrec[4 * m + 3], hb.y, acc3);
        }
        {
            const ulonglong2* x2 = reinterpret_cast<const ulonglong2*>(
                &S.xring[(t >> 6) & 1][(t & 63) * 8]);
            ulonglong2 xv = x2[0];
            ulonglong2 xw = x2[1];
            acc0 = fma2(wih2[0], xv.x, acc0);
            acc1 = fma2(wih2[1], xv.y, acc1);
            acc2 = fma2(wih2[2], xw.x, acc2);
            acc3 = fma2(wih2[3], xw.y, acc3);
        }
        ull s2 = add2(add2(acc0, acc1), add2(acc2, acc3));
        float2 sf = unpack2(s2);
        float a = fmaf(act_m, htanh(act_s * (sf.x + sf.y)), act_b);

        // gather the nibble's 4 gates via 2 shuffle levels
        float r1 = __shfl_xor_sync(0xFFFFFFFFu, a, 1);
        float r2 = __shfl_xor_sync(0xFFFFFFFFu, a, 2);
        float r3 = __shfl_xor_sync(0xFFFFFFFFu, r1, 2);
        if (gi == 0) {
            // a=i, r1=f, r2=g, r3=o
            c = r1 * c + a * r2;
            S.h[(t & 1) ^ 1][u] = r3 * htanh(c);
        }
        asm volatile("bar.sync %0, 256;" :: "r"(barid) : "memory");
    }

    // ---- backward direction: ONE step on x[T-1] from zero state ----
    {
        const float* xl = &S.xring[1][63 * 8];   // t=2047 -> buf 1, slot 63
        float zb = bih_b[r] + bhh_b[r];
#pragma unroll
        for (int i = 0; i < INP; i++) zb += Wih_b[r * INP + i] * xl[i];
        float a = fmaf(act_m, htanh(act_s * zb), act_b);
        float r1 = __shfl_xor_sync(0xFFFFFFFFu, a, 1);
        float r2 = __shfl_xor_sync(0xFFFFFFFFu, a, 2);
        float r3 = __shfl_xor_sync(0xFFFFFFFFu, r1, 2);
        if (gi == 0) {
            float cb = a * r2;                 // f*c0 == 0
            S.hb[u] = r3 * htanh(cb);
        }
        asm volatile("bar.sync %0, 256;" :: "r"(barid) : "memory");
    }

    // ---- final linear: out[b] = W_lin @ concat(h_f, h_b) + b_lin ----
    // final forward h was written into S.h[0] (t=2047 writes buffer (2047&1)^1 = 0)
    if (w < 3) {
        float a = blin[w];
#pragma unroll 16
        for (int k = 0; k < 64; k++) a += Wlin[w * 128 + k] * S.h[0][k];
#pragma unroll 16
        for (int k = 0; k < 64; k++) a += Wlin[w * 128 + 64 + k] * S.hb[k];
        out[b * 3 + w] = a;
    }
}

extern "C" void kernel_launch(void* const* d_in, const int* in_sizes, int n_in,
                              void* d_out, int out_size) {
    (void)in_sizes; (void)n_in; (void)out_size;
    bilstm_kernel<<<BATCH / 2, 512>>>(
        (const float*)d_in[0],  (const float*)d_in[1], (const float*)d_in[2],
        (const float*)d_in[3],  (const float*)d_in[4], (const float*)d_in[5],
        (const float*)d_in[6],  (const float*)d_in[7], (const float*)d_in[8],
        (const float*)d_in[9],  (const float*)d_in[10], (float*)d_out);
}

// round 5
// speedup vs baseline: 1.8463x; 1.1262x over previous
#include <cuda_runtime.h>
#include <cstdint>

#define T_SEQ 2048
#define BATCH 256
#define HID   64
#define INP   7
#define XSTEPS 64                    // steps per prefetch block
#define XBLK_FLOATS (XSTEPS * INP)   // 448 floats per block in GMEM

typedef unsigned long long ull;

__device__ __forceinline__ ull fma2(ull a, ull b, ull c) {
    ull d;
    asm("fma.rn.f32x2 %0, %1, %2, %3;" : "=l"(d) : "l"(a), "l"(b), "l"(c));
    return d;
}
__device__ __forceinline__ ull add2(ull a, ull b) {
    ull d;
    asm("add.rn.f32x2 %0, %1, %2;" : "=l"(d) : "l"(a), "l"(b));
    return d;
}
__device__ __forceinline__ ull pack2(float lo, float hi) {
    ull d; asm("mov.b64 %0, {%1, %2};" : "=l"(d) : "f"(lo), "f"(hi)); return d;
}
__device__ __forceinline__ float2 unpack2(ull a) {
    float2 r; asm("mov.b64 {%0, %1}, %2;" : "=f"(r.x), "=f"(r.y) : "l"(a)); return r;
}
__device__ __forceinline__ float htanh(float x) {
    float y; asm("tanh.approx.f32 %0, %1;" : "=f"(y) : "f"(x)); return y;
}
__device__ __forceinline__ void cpa4(uint32_t dst_smem, const float* src) {
    asm volatile("cp.async.ca.shared.global [%0], [%1], 4;" :: "r"(dst_smem), "l"(src));
}
__device__ __forceinline__ void cp_commit() {
    asm volatile("cp.async.commit_group;" ::: "memory");
}
__device__ __forceinline__ void cp_wait0() {
    asm volatile("cp.async.wait_group 0;" ::: "memory");
}

// grid = 128 CTAs x 256 threads; CTA runs 2 independent batch chains
// (chain = tid>>7), each chain = 128 threads = 4 warps, per-chain named bars.
//
// Each thread owns TWO gate rows of the same hidden unit u = (w>>1):
//   p = w&1;  rowA = p*64 + u   (p=0 -> gate i, p=1 -> gate f)
//             rowB = rowA + 128 (p=0 -> gate g, p=1 -> gate o)
// so the per-step 256B h broadcast (16 LDS.128) feeds 72 FMA2 instead of 36
// (halves LSU issue pressure vs 1-row-per-thread). Gate exchange needs one
// shfl_xor(1) level: p=0 holds (i,g), receives (f,o), updates c and writes h.
// ONE named barrier per step; h double-buffered to be WAR-safe.
// x streamed via cp.async double-buffered 64-step ring (8-float padded rows).
//
// Backward direction = ONE LSTM step on x[T-1] from zero state (scan[0] of
// the reversed sequence), fused as an epilogue with the final linear.
struct ChainSmem {
    float h[2][64];             // double-buffered hidden state
    float hb[64];               // backward h (epilogue)
    float xring[2][XSTEPS * 8]; // padded x ring, 2 blocks
};

__global__ void __launch_bounds__(256, 1)
bilstm_kernel(const float* __restrict__ x,      // [B,T,I]
              const float* __restrict__ Wih_f,  // [256,7]
              const float* __restrict__ Whh_f,  // [256,64]
              const float* __restrict__ bih_f,  // [256]
              const float* __restrict__ bhh_f,  // [256]
              const float* __restrict__ Wih_b,  // [256,7]
              const float* __restrict__ Whh_b,  // unused (h0 = 0 for single bwd step)
              const float* __restrict__ bih_b,  // [256]
              const float* __restrict__ bhh_b,  // [256]
              const float* __restrict__ Wlin,   // [3,128]
              const float* __restrict__ blin,   // [3]
              float* __restrict__ out)          // [B,3]
{
    __shared__ __align__(16) ChainSmem cs[2];

    const int tid   = threadIdx.x;
    const int chain = tid >> 7;          // 0 or 1
    const int w     = tid & 127;         // within-chain thread id
    const int p     = w & 1;             // gate pair selector
    const int u     = w >> 1;            // hidden unit
    const int rA    = p * 64 + u;        // gate i (p=0) / f (p=1)
    const int rB    = rA + 128;          // gate g (p=0) / o (p=1)
    const int b     = blockIdx.x * 2 + chain;
    const int barid = 1 + chain;
    ChainSmem& S = cs[chain];

    const float* xb = x + (size_t)b * T_SEQ * INP;

    const uint32_t ring0 = (uint32_t)__cvta_generic_to_shared(&S.xring[0][0]);
    const uint32_t ring1 = (uint32_t)__cvta_generic_to_shared(&S.xring[1][0]);

    // each thread copies 4 of the 512 floats per block
    const int e0 = 4 * w;
    const int s0 = e0 >> 3, j0 = e0 & 7;     // j0 in {0,4}; j0..j0+3

    // activation of row B: tanh for p=0 (gate g), sigmoid for p=1 (gate o)
    const float actB_s = (p == 0) ? 1.0f : 0.5f;
    const float actB_m = (p == 0) ? 1.0f : 0.5f;
    const float actB_b = (p == 0) ? 0.0f : 0.5f;

    // ---- weights into registers: 2 rows x 32 f32x2 ----
    ull wA[32], wB[32];
    {
        const ull* a = reinterpret_cast<const ull*>(Whh_f + rA * HID);
        const ull* c2 = reinterpret_cast<const ull*>(Whh_f + rB * HID);
#pragma unroll
        for (int m = 0; m < 32; m++) wA[m] = a[m];
#pragma unroll
        for (int m = 0; m < 32; m++) wB[m] = c2[m];
    }
    ull wihA[4], wihB[4];
    {
        float t[8];
#pragma unroll
        for (int i = 0; i < INP; i++) t[i] = Wih_f[rA * INP + i];
        t[7] = 0.0f;
#pragma unroll
        for (int m = 0; m < 4; m++) wihA[m] = pack2(t[2 * m], t[2 * m + 1]);
#pragma unroll
        for (int i = 0; i < INP; i++) t[i] = Wih_f[rB * INP + i];
        t[7] = 0.0f;
#pragma unroll
        for (int m = 0; m < 4; m++) wihB[m] = pack2(t[2 * m], t[2 * m + 1]);
    }
    const float biasA = bih_f[rA] + bhh_f[rA];
    const float biasB = bih_f[rB] + bhh_f[rB];

    // ---- init: h=0, zero ring pad slots, prefetch blocks 0 and 1 ----
    if (w < 64) S.h[0][w] = 0.0f;
    {   // zero the j==7 pad slot of all 128 ring rows (2 bufs x 64 slots)
        int bufi = w >> 6, s = w & 63;
        S.xring[bufi][s * 8 + 7] = 0.0f;
        S.xring[(bufi ^ 1)][s * 8 + 7] = 0.0f;
    }
#pragma unroll
    for (int k = 0; k < 4; k++)
        if (j0 + k < 7) cpa4(ring0 + (uint32_t)(e0 + k) * 4, xb + s0 * INP + j0 + k);
    cp_commit();
#pragma unroll
    for (int k = 0; k < 4; k++)
        if (j0 + k < 7) cpa4(ring1 + (uint32_t)(e0 + k) * 4, xb + XBLK_FLOATS + s0 * INP + j0 + k);
    cp_commit();
    cp_wait0();
    float c = 0.0f;
    __syncthreads();

    for (int t = 0; t < T_SEQ; t++) {
        if ((t & (XSTEPS - 1)) == 0 && t) {
            cp_wait0();   // block issued 64 steps ago has landed
            asm volatile("bar.sync %0, 128;" :: "r"(barid) : "memory");
            int nb = (t >> 6) + 1;
            if (nb < T_SEQ / XSTEPS) {
                uint32_t dst = (nb & 1) ? ring1 : ring0;
                const float* src = xb + (size_t)nb * XBLK_FLOATS;
#pragma unroll
                for (int k = 0; k < 4; k++)
                    if (j0 + k < 7) cpa4(dst + (uint32_t)(e0 + k) * 4, src + s0 * INP + j0 + k);
            }
            cp_commit();
        }

        // z = W_hh·h + W_ih·x + bias for both rows (h/x LDS shared by 2 rows)
        ull a0 = pack2(biasA, 0.0f), a1 = 0ull;
        ull b0 = pack2(biasB, 0.0f), b1 = 0ull;
        const ulonglong2* h2 = reinterpret_cast<const ulonglong2*>(S.h[t & 1]);
#pragma unroll
        for (int m = 0; m < 8; m++) {
            ulonglong2 ha = h2[2 * m];
            ulonglong2 hbv = h2[2 * m + 1];
            a0 = fma2(wA[4 * m + 0], ha.x,  a0);
            a1 = fma2(wA[4 * m + 1], ha.y,  a1);
            b0 = fma2(wB[4 * m + 0], ha.x,  b0);
            b1 = fma2(wB[4 * m + 1], ha.y,  b1);
            a0 = fma2(wA[4 * m + 2], hbv.x, a0);
            a1 = fma2(wA[4 * m + 3], hbv.y, a1);
            b0 = fma2(wB[4 * m + 2], hbv.x, b0);
            b1 = fma2(wB[4 * m + 3], hbv.y, b1);
        }
        {
            const ulonglong2* x2 = reinterpret_cast<const ulonglong2*>(
                &S.xring[(t >> 6) & 1][(t & 63) * 8]);
            ulonglong2 xv = x2[0];
            ulonglong2 xw = x2[1];
            a0 = fma2(wihA[0], xv.x, a0);
            a1 = fma2(wihA[1], xv.y, a1);
            b0 = fma2(wihB[0], xv.x, b0);
            b1 = fma2(wihB[1], xv.y, b1);
            a0 = fma2(wihA[2], xw.x, a0);
            a1 = fma2(wihA[3], xw.y, a1);
            b0 = fma2(wihB[2], xw.x, b0);
            b1 = fma2(wihB[3], xw.y, b1);
        }
        float2 sfA = unpack2(add2(a0, a1));
        float2 sfB = unpack2(add2(b0, b1));
        float zA = sfA.x + sfA.y;
        float zB = sfB.x + sfB.y;

        // activations: row A always sigmoid (i or f); row B tanh (g) / sigmoid (o)
        float aA = fmaf(0.5f, htanh(0.5f * zA), 0.5f);
        float aB = fmaf(actB_m, htanh(actB_s * zB), actB_b);

        // exchange within lane pair: p=0 holds (i,g); gets (f,o) from p=1
        float oA = __shfl_xor_sync(0xFFFFFFFFu, aA, 1);   // p=0 receives f
        float oB = __shfl_xor_sync(0xFFFFFFFFu, aB, 1);   // p=0 receives o
        if (p == 0) {
            c = oA * c + aA * aB;                 // c = f*c + i*g
            S.h[(t & 1) ^ 1][u] = oB * htanh(c);  // h = o*tanh(c)
        }
        asm volatile("bar.sync %0, 128;" :: "r"(barid) : "memory");
    }

    // ---- backward direction: ONE step on x[T-1] from zero state ----
    {
        const float* xl = &S.xring[1][63 * 8];   // t=2047 -> buf 1, slot 63
        float zbA = bih_b[rA] + bhh_b[rA];
        float zbB = bih_b[rB] + bhh_b[rB];
#pragma unroll
        for (int i = 0; i < INP; i++) {
            zbA += Wih_b[rA * INP + i] * xl[i];
            zbB += Wih_b[rB * INP + i] * xl[i];
        }
        float aA = fmaf(0.5f, htanh(0.5f * zbA), 0.5f);
        float aB = fmaf(actB_m, htanh(actB_s * zbB), actB_b);
        float oA = __shfl_xor_sync(0xFFFFFFFFu, aA, 1);   // f (unused: c0=0)
        float oB = __shfl_xor_sync(0xFFFFFFFFu, aB, 1);   // o
        (void)oA;
        if (p == 0) {
            float cb = aA * aB;                  // i*g (f*c0 == 0)
            S.hb[u] = oB * htanh(cb);
        }
        asm volatile("bar.sync %0, 128;" :: "r"(barid) : "memory");
    }

    // ---- final linear: out[b] = W_lin @ concat(h_f, h_b) + b_lin ----
    // final forward h is in S.h[0] (t=2047 writes buffer (2047&1)^1 = 0)
    if (w < 3) {
        float a = blin[w];
#pragma unroll 16
        for (int k = 0; k < 64; k++) a += Wlin[w * 128 + k] * S.h[0][k];
#pragma unroll 16
        for (int k = 0; k < 64; k++) a += Wlin[w * 128 + 64 + k] * S.hb[k];
        out[b * 3 + w] = a;
    }
}

extern "C" void kernel_launch(void* const* d_in, const int* in_sizes, int n_in,
                              void* d_out, int out_size) {
    (void)in_sizes; (void)n_in; (void)out_size;
    bilstm_kernel<<<BATCH / 2, 256>>>(
        (const float*)d_in[0],  (const float*)d_in[1], (const float*)d_in[2],
        (const float*)d_in[3],  (const float*)d_in[4], (const float*)d_in[5],
        (const float*)d_in[6],  (const float*)d_in[7], (const float*)d_in[8],
        (const float*)d_in[9],  (const float*)d_in[10], (float*)d_out);
}

// round 7
// speedup vs baseline: 1.8881x; 1.0226x over previous
#include <cuda_runtime.h>
#include <cstdint>

#define T_SEQ 2048
#define BATCH 256
#define HID   64
#define INP   7
#define XSTEPS 64                    // steps per prefetch block
#define XBLK_FLOATS (XSTEPS * INP)   // 448 floats per block in GMEM

typedef unsigned long long ull;

__device__ __forceinline__ ull fma2(ull a, ull b, ull c) {
    ull d;
    asm("fma.rn.f32x2 %0, %1, %2, %3;" : "=l"(d) : "l"(a), "l"(b), "l"(c));
    return d;
}
__device__ __forceinline__ ull add2(ull a, ull b) {
    ull d;
    asm("add.rn.f32x2 %0, %1, %2;" : "=l"(d) : "l"(a), "l"(b));
    return d;
}
__device__ __forceinline__ ull pack2(float lo, float hi) {
    ull d; asm("mov.b64 %0, {%1, %2};" : "=l"(d) : "f"(lo), "f"(hi)); return d;
}
__device__ __forceinline__ float2 unpack2(ull a) {
    float2 r; asm("mov.b64 {%0, %1}, %2;" : "=f"(r.x), "=f"(r.y) : "l"(a)); return r;
}
__device__ __forceinline__ float htanh(float x) {
    float y; asm("tanh.approx.f32 %0, %1;" : "=f"(y) : "f"(x)); return y;
}
__device__ __forceinline__ void cpa4(uint32_t dst_smem, const float* src) {
    asm volatile("cp.async.ca.shared.global [%0], [%1], 4;" :: "r"(dst_smem), "l"(src));
}
__device__ __forceinline__ void cp_commit() {
    asm volatile("cp.async.commit_group;" ::: "memory");
}
__device__ __forceinline__ void cp_wait0() {
    asm volatile("cp.async.wait_group 0;" ::: "memory");
}

// grid = 128 CTAs x 256 threads; CTA runs 2 independent batch chains
// (chain = tid>>7), each chain = 128 threads = 4 warps, per-chain named bars.
// The two chains are deliberately STAGGERED by ~half a step (one-time
// dependent-FMA delay on chain 1 after the init sync): since both chains take
// identical per-step time, the anti-phase offset persists, so one chain's
// serial tail (MUFU/SHFL/BAR/LDS) overlaps the other chain's FMA phase.
//
// Each thread owns TWO gate rows of hidden unit u = (w>>1):
//   p = w&1;  rowA = p*64 + u (i/f),  rowB = rowA + 128 (g/o)
// z-phase reads the 256B h broadcast as 16 LDS.128 feeding 64 FMA2.
// The x·Wih + bias part (xz) is h-independent and precomputed in the tail
// shadow of the previous step. Gate exchange = one shfl_xor(1); p==0 lanes
// update c and write h (double-buffered). ONE named barrier per step.
// x streamed via cp.async double-buffered 64-step ring (8-float padded rows).
//
// Backward direction = ONE LSTM step on x[T-1] from zero state, fused with
// the final linear as an epilogue.
struct ChainSmem {
    float h[2][64];             // double-buffered hidden state
    float hb[64];               // backward h (epilogue)
    float xring[2][XSTEPS * 8]; // padded x ring, 2 blocks
};

__global__ void __launch_bounds__(256, 1)
bilstm_kernel(const float* __restrict__ x,      // [B,T,I]
              const float* __restrict__ Wih_f,  // [256,7]
              const float* __restrict__ Whh_f,  // [256,64]
              const float* __restrict__ bih_f,  // [256]
              const float* __restrict__ bhh_f,  // [256]
              const float* __restrict__ Wih_b,  // [256,7]
              const float* __restrict__ Whh_b,  // unused (h0 = 0 for single bwd step)
              const float* __restrict__ bih_b,  // [256]
              const float* __restrict__ bhh_b,  // [256]
              const float* __restrict__ Wlin,   // [3,128]
              const float* __restrict__ blin,   // [3]
              float* __restrict__ out)          // [B,3]
{
    __shared__ __align__(16) ChainSmem cs[2];

    const int tid   = threadIdx.x;
    const int chain = tid >> 7;          // 0 or 1
    const int w     = tid & 127;         // within-chain thread id
    const int p     = w & 1;             // gate pair selector
    const int u     = w >> 1;            // hidden unit
    const int rA    = p * 64 + u;        // gate i (p=0) / f (p=1)
    const int rB    = rA + 128;          // gate g (p=0) / o (p=1)
    const int b     = blockIdx.x * 2 + chain;
    const int barid = 1 + chain;
    ChainSmem& S = cs[chain];

    const float* xb = x + (size_t)b * T_SEQ * INP;

    const uint32_t ring0 = (uint32_t)__cvta_generic_to_shared(&S.xring[0][0]);
    const uint32_t ring1 = (uint32_t)__cvta_generic_to_shared(&S.xring[1][0]);

    // each thread copies 4 of the 512 floats per block
    const int e0 = 4 * w;
    const int s0 = e0 >> 3, j0 = e0 & 7;     // j0 in {0,4}

    // activation of row B: tanh for p=0 (gate g), sigmoid for p=1 (gate o)
    const float actB_s = (p == 0) ? 1.0f : 0.5f;
    const float actB_m = (p == 0) ? 1.0f : 0.5f;
    const float actB_b = (p == 0) ? 0.0f : 0.5f;

    // ---- weights into registers: 2 rows x 32 f32x2 ----
    ull wA[32], wB[32];
    {
        const ull* a = reinterpret_cast<const ull*>(Whh_f + rA * HID);
        const ull* c2 = reinterpret_cast<const ull*>(Whh_f + rB * HID);
#pragma unroll
        for (int m = 0; m < 32; m++) wA[m] = a[m];
#pragma unroll
        for (int m = 0; m < 32; m++) wB[m] = c2[m];
    }
    ull wihA[4], wihB[4];
    {
        float t[8];
#pragma unroll
        for (int i = 0; i < INP; i++) t[i] = Wih_f[rA * INP + i];
        t[7] = 0.0f;
#pragma unroll
        for (int m = 0; m < 4; m++) wihA[m] = pack2(t[2 * m], t[2 * m + 1]);
#pragma unroll
        for (int i = 0; i < INP; i++) t[i] = Wih_f[rB * INP + i];
        t[7] = 0.0f;
#pragma unroll
        for (int m = 0; m < 4; m++) wihB[m] = pack2(t[2 * m], t[2 * m + 1]);
    }
    const float biasA = bih_f[rA] + bhh_f[rA];
    const float biasB = bih_f[rB] + bhh_f[rB];

    // ---- init: h=0, zero ring pad slots, prefetch blocks 0 and 1 ----
    if (w < 64) S.h[0][w] = 0.0f;
    {
        int bufi = w >> 6, s = w & 63;
        S.xring[bufi][s * 8 + 7] = 0.0f;
        S.xring[(bufi ^ 1)][s * 8 + 7] = 0.0f;
    }
#pragma unroll
    for (int k = 0; k < 4; k++)
        if (j0 + k < 7) cpa4(ring0 + (uint32_t)(e0 + k) * 4, xb + s0 * INP + j0 + k);
    cp_commit();
#pragma unroll
    for (int k = 0; k < 4; k++)
        if (j0 + k < 7) cpa4(ring1 + (uint32_t)(e0 + k) * 4, xb + XBLK_FLOATS + s0 * INP + j0 + k);
    cp_commit();
    cp_wait0();
    float c = 0.0f;
    __syncthreads();

    // ---- one-time stagger: chain 1 burns ~320 cycles in a dependent FMA
    // chain so the two chains run anti-phase for the whole sequence ----
    if (chain == 1) {
        float d = biasA + 1.5f;
#pragma unroll
        for (int i = 0; i < 80; i++) d = fmaf(d, 0.9999999f, 1e-9f);
        asm volatile("" :: "f"(d));   // opaque sink, no DCE
    }

    // xz accumulators for the CURRENT step (h-independent part + bias)
    ull xzA0, xzA1, xzB0, xzB1;
    {
        const ulonglong2* x2 = reinterpret_cast<const ulonglong2*>(&S.xring[0][0]);
        ulonglong2 xv = x2[0];
        ulonglong2 xw = x2[1];
        xzA0 = fma2(wihA[0], xv.x, pack2(biasA, 0.0f));
        xzA1 = fma2(wihA[1], xv.y, 0ull);
        xzB0 = fma2(wihB[0], xv.x, pack2(biasB, 0.0f));
        xzB1 = fma2(wihB[1], xv.y, 0ull);
        xzA0 = fma2(wihA[2], xw.x, xzA0);
        xzA1 = fma2(wihA[3], xw.y, xzA1);
        xzB0 = fma2(wihB[2], xw.x, xzB0);
        xzB1 = fma2(wihB[3], xw.y, xzB1);
    }

    for (int t = 0; t < T_SEQ; t++) {
        if ((t & (XSTEPS - 1)) == 0 && t) {
            cp_wait0();   // block issued 64 steps ago has landed
            asm volatile("bar.sync %0, 128;" :: "r"(barid) : "memory");
            int nb = (t >> 6) + 1;
            if (nb < T_SEQ / XSTEPS) {
                uint32_t dst = (nb & 1) ? ring1 : ring0;
                const float* src = xb + (size_t)nb * XBLK_FLOATS;
#pragma unroll
                for (int k = 0; k < 4; k++)
                    if (j0 + k < 7) cpa4(dst + (uint32_t)(e0 + k) * 4, src + s0 * INP + j0 + k);
            }
            cp_commit();
            // boundary step: xz for THIS step from the just-waited buffer
            const ulonglong2* x2 = reinterpret_cast<const ulonglong2*>(
                &S.xring[(t >> 6) & 1][(t & 63) * 8]);
            ulonglong2 xv = x2[0];
            ulonglong2 xw = x2[1];
            xzA0 = fma2(wihA[0], xv.x, pack2(biasA, 0.0f));
            xzA1 = fma2(wihA[1], xv.y, 0ull);
            xzB0 = fma2(wihB[0], xv.x, pack2(biasB, 0.0f));
            xzB1 = fma2(wihB[1], xv.y, 0ull);
            xzA0 = fma2(wihA[2], xw.x, xzA0);
            xzA1 = fma2(wihA[3], xw.y, xzA1);
            xzB0 = fma2(wihB[2], xw.x, xzB0);
            xzB1 = fma2(wihB[3], xw.y, xzB1);
        }

        // z = xz + W_hh·h  (h broadcast LDS shared by both rows)
        ull a0 = xzA0, a1 = xzA1;
        ull b0 = xzB0, b1 = xzB1;
        const ulonglong2* h2 = reinterpret_cast<const ulonglong2*>(S.h[t & 1]);
#pragma unroll
        for (int m = 0; m < 8; m++) {
            ulonglong2 ha = h2[2 * m];
            ulonglong2 hbv = h2[2 * m + 1];
            a0 = fma2(wA[4 * m + 0], ha.x,  a0);
            a1 = fma2(wA[4 * m + 1], ha.y,  a1);
            b0 = fma2(wB[4 * m + 0], ha.x,  b0);
            b1 = fma2(wB[4 * m + 1], ha.y,  b1);
            a0 = fma2(wA[4 * m + 2], hbv.x, a0);
            a1 = fma2(wA[4 * m + 3], hbv.y, a1);
            b0 = fma2(wB[4 * m + 2], hbv.x, b0);
            b1 = fma2(wB[4 * m + 3], hbv.y, b1);
        }
        float2 sfA = unpack2(add2(a0, a1));
        float2 sfB = unpack2(add2(b0, b1));
        float zA = sfA.x + sfA.y;
        float zB = sfB.x + sfB.y;

        // activations: row A sigmoid (i or f); row B tanh (g) / sigmoid (o)
        float aA = fmaf(0.5f, htanh(0.5f * zA), 0.5f);
        float aB = fmaf(actB_m, htanh(actB_s * zB), actB_b);

        // exchange within lane pair: p=0 holds (i,g); gets (f,o) from p=1
        float oA = __shfl_xor_sync(0xFFFFFFFFu, aA, 1);
        float oB = __shfl_xor_sync(0xFFFFFFFFu, aB, 1);
        if (p == 0) {
            c = oA * c + aA * aB;                 // c = f*c + i*g
            S.h[(t & 1) ^ 1][u] = oB * htanh(c);  // h = o*tanh(c)
        }

        // tail shadow: precompute xz for step t+1 (non-boundary successors)
        if (((t + 1) & (XSTEPS - 1)) != 0 && t + 1 < T_SEQ) {
            const ulonglong2* x2 = reinterpret_cast<const ulonglong2*>(
                &S.xring[((t + 1) >> 6) & 1][((t + 1) & 63) * 8]);
            ulonglong2 xv = x2[0];
            ulonglong2 xw = x2[1];
            xzA0 = fma2(wihA[0], xv.x, pack2(biasA, 0.0f));
            xzA1 = fma2(wihA[1], xv.y, 0ull);
            xzB0 = fma2(wihB[0], xv.x, pack2(biasB, 0.0f));
            xzB1 = fma2(wihB[1], xv.y, 0ull);
            xzA0 = fma2(wihA[2], xw.x, xzA0);
            xzA1 = fma2(wihA[3], xw.y, xzA1);
            xzB0 = fma2(wihB[2], xw.x, xzB0);
            xzB1 = fma2(wihB[3], xw.y, xzB1);
        }
        asm volatile("bar.sync %0, 128;" :: "r"(barid) : "memory");
    }

    // ---- backward direction: ONE step on x[T-1] from zero state ----
    {
        const float* xl = &S.xring[1][63 * 8];   // t=2047 -> buf 1, slot 63
        float zbA = bih_b[rA] + bhh_b[rA];
        float zbB = bih_b[rB] + bhh_b[rB];
#pragma unroll
        for (int i = 0; i < INP; i++) {
            zbA += Wih_b[rA * INP + i] * xl[i];
            zbB += Wih_b[rB * INP + i] * xl[i];
        }
        float aA = fmaf(0.5f, htanh(0.5f * zbA), 0.5f);
        float aB = fmaf(actB_m, htanh(actB_s * zbB), actB_b);
        float oB = __shfl_xor_sync(0xFFFFFFFFu, aB, 1);   // o
        if (p == 0) {
            float cb = aA * aB;                  // i*g (f*c0 == 0)
            S.hb[u] = oB * htanh(cb);
        }
        asm volatile("bar.sync %0, 128;" :: "r"(barid) : "memory");
    }

    // ---- final linear: out[b] = W_lin @ concat(h_f, h_b) + b_lin ----
    // final forward h is in S.h[0] (t=2047 writes buffer (2047&1)^1 = 0)
    if (w < 3) {
        float a = blin[w];
#pragma unroll 16
        for (int k = 0; k < 64; k++) a += Wlin[w * 128 + k] * S.h[0][k];
#pragma unroll 16
        for (int k = 0; k < 64; k++) a += Wlin[w * 128 + 64 + k] * S.hb[k];
        out[b * 3 + w] = a;
    }
}

extern "C" void kernel_launch(void* const* d_in, const int* in_sizes, int n_in,
                              void* d_out, int out_size) {
    (void)in_sizes; (void)n_in; (void)out_size;
    bilstm_kernel<<<BATCH / 2, 256>>>(
        (const float*)d_in[0],  (const float*)d_in[1], (const float*)d_in[2],
        (const float*)d_in[3],  (const float*)d_in[4], (const float*)d_in[5],
        (const float*)d_in[6],  (const float*)d_in[7], (const float*)d_in[8],
        (const float*)d_in[9],  (const float*)d_in[10], (float*)d_out);
}